// round 15
// baseline (speedup 1.0000x reference)
#include <cuda_runtime.h>
#include <math.h>

// 21-qubit / 3-layer QNN statevector sim; double-buffered inter-pass layout staging.
// Pair format: float4(re(2h),re(2h+1),im(2h),im(2h+1)); amp bit k <-> qubit 20-k;
// amp bit 0 = float4 lane; pair bit b = amp bit b+1.
//
// Buffers (fixed roles):
//   d_sB (written by A, read by B):  a = [p0 | p9..11 @a1..3 | p12..19 @a4..11 | p1..8 @a12..19]
//   d_sA (written by B, read by A):  a = [p0 | p9..11 @a1..3 | p1..8  @a4..11 | p12..19 @a12..19]
// Each reader's 12 tile bits are its LOW 12 address bits -> coalesced loads.
//
// passA: Rot amps 0..10 + CNOT targets 0..9 (perm + lane swap folded into store).
// passB: Rot amps 11..20 + CNOT targets 10..19 (perm folded into store).
// 2 rounds/pass, 1 smem trip; shuffle-gates on lane bits; layer0 A does gate prep.

#define NQ      21
#define NPAIR   (1u << 20)
#define THREADS 512
#define TILEP   4096
#define SMEMB   (TILEP * 16 + 768)
#define NBLK    256

typedef unsigned long long u64;

__device__ float4 d_sA[NPAIR];   // A reads, B writes
__device__ float4 d_sB[NPAIR];   // A writes, B reads

struct Gate2 { u64 p, q, mq, r, mr, s, ms; };
__device__ Gate2 d_gates[3][NQ];
struct Gate0 { u64 v[6]; };              // (p,p)(r,-r)(-q,q)(-s,-s)(q,-q)(s,s)
__device__ Gate0 d_gate0[3];

__device__ __forceinline__ u64 fma2(u64 a, u64 b, u64 c) {
    u64 d; asm("fma.rn.f32x2 %0,%1,%2,%3;" : "=l"(d) : "l"(a), "l"(b), "l"(c)); return d;
}
__device__ __forceinline__ u64 mul2(u64 a, u64 b) {
    u64 d; asm("mul.rn.f32x2 %0,%1,%2;" : "=l"(d) : "l"(a), "l"(b)); return d;
}
__device__ __forceinline__ float flo(u64 v) { return __uint_as_float((unsigned)v); }
__device__ __forceinline__ float fhi(u64 v) { return __uint_as_float((unsigned)(v >> 32)); }
__device__ __forceinline__ u64 fpack(float a, float b) {
    return (u64)__float_as_uint(a) | ((u64)__float_as_uint(b) << 32);
}
__device__ __forceinline__ u64 swap64(u64 v) { return (v >> 32) | (v << 32); }
__device__ __forceinline__ unsigned sw(unsigned l) { return l ^ ((l >> 3) & 7u); }

__device__ __forceinline__ void gate_coeffs(const float* __restrict__ pp,
                                            float& p, float& q, float& r, float& sv) {
    float phi = pp[0], th = pp[1], om = pp[2];
    float s, c;   sincosf(0.5f * th, &s, &c);
    float sa, ca; sincosf(0.5f * (phi + om), &sa, &ca);
    float sb, cb; sincosf(0.5f * (phi - om), &sb, &cb);
    p = ca * c; q = -sa * c; r = -cb * s; sv = -sb * s;
}

template<int S>
__device__ __forceinline__ void vgate(u64 (&re)[8], u64 (&im)[8], const u64* __restrict__ g) {
    const u64 p = g[0], q = g[1], mq = g[2], r = g[3], mr = g[4], s = g[5], ms = g[6];
#pragma unroll
    for (int j = 0; j < 8; j++) {
        if (j & S) continue;
        const int j1 = j | S;
        u64 xr = re[j], xi = im[j], yr = re[j1], yi = im[j1];
        u64 nr0 = fma2(ms, yi, fma2(r,  yr, fma2(mq, xi, mul2(p,  xr))));
        u64 ni0 = fma2(r,  yi, fma2(s,  yr, fma2(p,  xi, mul2(q,  xr))));
        u64 nr1 = fma2(q,  yi, fma2(p,  yr, fma2(ms, xi, mul2(mr, xr))));
        u64 ni1 = fma2(p,  yi, fma2(mq, yr, fma2(mr, xi, mul2(s,  xr))));
        re[j] = nr0; im[j] = ni0; re[j1] = nr1; im[j1] = ni1;
    }
}

template<int B>
__device__ __forceinline__ void hgate(u64 (&re)[8], u64 (&im)[8], const u64* __restrict__ g) {
    const u64 p = g[0], s = g[5], ms = g[6];
    const bool hi = (threadIdx.x >> B) & 1;
    const u64 A  = hi ? g[1] : g[2];
    const u64 C  = hi ? g[2] : g[1];
    const u64 Bc = hi ? g[4] : g[3];
#pragma unroll
    for (int j = 0; j < 8; j++) {
        u64 wr = __shfl_xor_sync(0xffffffffu, re[j], 1 << B);
        u64 wi = __shfl_xor_sync(0xffffffffu, im[j], 1 << B);
        u64 nr = fma2(ms, wi, fma2(Bc, wr, fma2(A, im[j], mul2(p, re[j]))));
        u64 ni = fma2(Bc, wi, fma2(s,  wr, fma2(p, im[j], mul2(C, re[j]))));
        re[j] = nr; im[j] = ni;
    }
}

__device__ __forceinline__ void sgate2(u64 (&re)[8], u64 (&im)[8], const u64* __restrict__ g) {
    const u64 pp = g[0], rmr = g[1], mqq = g[2], msms = g[3], qmq = g[4], ss = g[5];
#pragma unroll
    for (int j = 0; j < 8; j++) {
        u64 sre = swap64(re[j]), sim = swap64(im[j]);
        u64 nr = fma2(msms, sim, fma2(mqq, im[j], fma2(rmr, sre, mul2(pp,  re[j]))));
        u64 ni = fma2(rmr,  sim, fma2(pp,  im[j], fma2(ss,  sre, mul2(qmq, re[j]))));
        re[j] = nr; im[j] = ni;
    }
}

__device__ __forceinline__ float4 packf4(u64 r, u64 i) {
    return make_float4(flo(r), fhi(r), flo(i), fhi(i));
}
__device__ __forceinline__ void unpackf4(float4 v, u64& r, u64& i) {
    r = fpack(v.x, v.y); i = fpack(v.z, v.w);
}

// r2 layout (both passes): t0..3->l0..3, t5->l4, j->l5..7, t4->l8, t6..8->l9..11
__device__ __forceinline__ unsigned r2i(unsigned t, unsigned j) {
    return (t & 15u) | (((t >> 5) & 1u) << 4) | (j << 5)
         | (((t >> 4) & 1u) << 8) | ((t >> 6) << 9);
}

// ============================ pass A ============================
// FIRST: locals = pairs 0..11 (identity, feat); blk = p12..19.
// else : reads d_sA; locals: l0=p0, l1..3=p9..11, l4..11=p1..8; blk = p12..19.
// Gates amps 0..10. Store to d_sB with CNOT perm (targets 0..9) + lane swap.
template<int LAYER, bool FIRST>
__global__ void __launch_bounds__(THREADS, 2)
passA_kernel(const float* __restrict__ feat, const float* __restrict__ param,
             float* __restrict__ out) {
    extern __shared__ char smraw[];
    float4* sm = reinterpret_cast<float4*>(smraw);
    u64* gsm = reinterpret_cast<u64*>(smraw + TILEP * 16);
    const unsigned t   = threadIdx.x;
    const unsigned blk = blockIdx.x;
    u64 re[8], im[8];

    if (FIRST) {
        if (t < 3 * NQ) {
            const int layer = t / NQ, bit = t % NQ, qubit = 20 - bit;
            float p, q, r, sv;
            gate_coeffs(param + (layer * NQ + qubit) * 3, p, q, r, sv);
            Gate2 g;
            g.p  = fpack(p, p);    g.q  = fpack(q, q);   g.mq = fpack(-q, -q);
            g.r  = fpack(r, r);    g.mr = fpack(-r, -r);
            g.s  = fpack(sv, sv);  g.ms = fpack(-sv, -sv);
            if (blk == 0) d_gates[layer][bit] = g;
            if (layer == 0 && bit >= 1 && bit <= 10) {
                u64* dst = gsm + 6 + (bit - 1) * 7;
                dst[0] = g.p;  dst[1] = g.q;  dst[2] = g.mq; dst[3] = g.r;
                dst[4] = g.mr; dst[5] = g.s;  dst[6] = g.ms;
            }
            if (bit == 0) {
                Gate0 g0;
                g0.v[0] = fpack(p, p);    g0.v[1] = fpack(r, -r);
                g0.v[2] = fpack(-q, q);   g0.v[3] = fpack(-sv, -sv);
                g0.v[4] = fpack(q, -q);   g0.v[5] = fpack(sv, sv);
                if (blk == 0) d_gate0[layer] = g0;
                if (layer == 0) {
#pragma unroll
                    for (int k = 0; k < 6; k++) gsm[k] = g0.v[k];
                }
            }
        }
        if (blk == 0 && t == 0) out[0] = 0.f;
    } else {
        // stage: gate0 + amps 1..10 at gsm[6 + (a-1)*7]
        if (t < 6)  gsm[t] = reinterpret_cast<const u64*>(&d_gate0[LAYER])[t];
        if (t < 70) gsm[6 + t] = reinterpret_cast<const u64*>(&d_gates[LAYER][1])[t];
    }

    // r1 load: l = t | (j<<9), coalesced
#pragma unroll
    for (int j = 0; j < 8; j++) {
        unsigned l = t | (j << 9);
        if (FIRST) {
            float2 fv = reinterpret_cast<const float2*>(feat)[(blk << 12) | l];
            re[j] = fpack(fv.x, fv.y); im[j] = 0ull;
        } else {
            unpackf4(d_sA[(blk << 12) | l], re[j], im[j]);
        }
    }
    __syncthreads();

    sgate2(re, im, gsm);                        // amp 0
    hgate<0>(re, im, gsm + 6);                  // amp 1  (l0 = p0)
    if (FIRST) {
        hgate<1>(re, im, gsm + 13);             // amp 2  (l1 = p1)
        hgate<2>(re, im, gsm + 20);             // amp 3
        hgate<3>(re, im, gsm + 27);             // amp 4
        hgate<4>(re, im, gsm + 34);             // amp 5
        vgate<1>(re, im, gsm + 69);             // amp 10 (l9 = p9, j bit 0)
    } else {
        hgate<1>(re, im, gsm + 69);             // amp 10 (l1 = p9)
        hgate<4>(re, im, gsm + 13);             // amp 2  (l4 = p1)
        vgate<1>(re, im, gsm + 48);             // amp 7  (l9 = p6)
        vgate<2>(re, im, gsm + 55);             // amp 8  (l10 = p7)
        vgate<4>(re, im, gsm + 62);             // amp 9  (l11 = p8)
    }
#pragma unroll
    for (int j = 0; j < 8; j++) sm[sw(t | (j << 9))] = packf4(re[j], im[j]);
    __syncthreads();

    // r2
#pragma unroll
    for (int j = 0; j < 8; j++) unpackf4(sm[sw(r2i(t, j))], re[j], im[j]);
    if (FIRST) {
        vgate<1>(re, im, gsm + 41);             // amp 6 (l5 = p5)
        vgate<2>(re, im, gsm + 48);             // amp 7
        vgate<4>(re, im, gsm + 55);             // amp 8
        hgate<4>(re, im, gsm + 62);             // amp 9 (t4 -> l8 = p8)
    } else {
        vgate<1>(re, im, gsm + 20);             // amp 3 (l5 = p2)
        vgate<2>(re, im, gsm + 27);             // amp 4
        vgate<4>(re, im, gsm + 34);             // amp 5
        hgate<4>(re, im, gsm + 41);             // amp 6 (t4 -> l8 = p5)
    }

    // perm (targets amps 0..9) in pair space, store to d_sB
#pragma unroll
    for (int j = 0; j < 8; j++) {
        unsigned l = r2i(t, j);
        unsigned z = FIRST ? l
            : ((l & 1u) | (((l >> 4) & 0xFFu) << 1) | (((l >> 1) & 7u) << 9));
        unsigned u = z ^ ((z >> 1) & 0x155u);
        unsigned zh = u ^ ((u >> 1) & 0xAAu);
        unsigned a = (zh & 1u) | (((zh >> 9) & 7u) << 1) | (blk << 4)
                   | (((zh >> 1) & 0xFFu) << 12);
        float4 v = packf4(re[j], im[j]);
        d_sB[a] = (zh & 1u) ? make_float4(v.y, v.x, v.w, v.z) : v;
    }
}

// ============================ pass B ============================
// Reads d_sB (coalesced): locals l0=p0, l1..3=p9..11, l4..11=p12..19; blk = p1..8.
// Gates amps 11..20. Stores d_sA with CNOT perm (targets 10..19 = l1..10) folded in.
template<int LAYER, bool LAST>
__global__ void __launch_bounds__(THREADS, 2)
passB_kernel(float* __restrict__ out) {
    extern __shared__ char smraw[];
    float4* sm = reinterpret_cast<float4*>(smraw);
    u64* gsm = reinterpret_cast<u64*>(smraw + TILEP * 16);
    const unsigned t = threadIdx.x;
    const unsigned blk = blockIdx.x;
    u64 re[8], im[8];

    // stage amps 11..20 at gsm[(a-11)*7]
    if (t < 70) gsm[t] = reinterpret_cast<const u64*>(&d_gates[LAYER][11])[t];

#pragma unroll
    for (int j = 0; j < 8; j++)
        unpackf4(d_sB[(blk << 12) | (t | (j << 9))], re[j], im[j]);
    __syncthreads();

    hgate<2>(re, im, gsm + 0);            // amp 11 (l2 = p10)
    hgate<3>(re, im, gsm + 7);            // amp 12 (l3 = p11)
    hgate<4>(re, im, gsm + 14);           // amp 13 (l4 = p12)
    vgate<1>(re, im, gsm + 49);           // amp 18 (l9 = p17)
    vgate<2>(re, im, gsm + 56);           // amp 19
    vgate<4>(re, im, gsm + 63);           // amp 20
#pragma unroll
    for (int j = 0; j < 8; j++) sm[sw(t | (j << 9))] = packf4(re[j], im[j]);
    __syncthreads();

#pragma unroll
    for (int j = 0; j < 8; j++) unpackf4(sm[sw(r2i(t, j))], re[j], im[j]);
    vgate<1>(re, im, gsm + 21);           // amp 14 (l5 = p13)
    vgate<2>(re, im, gsm + 28);           // amp 15
    vgate<4>(re, im, gsm + 35);           // amp 16
    hgate<4>(re, im, gsm + 42);           // amp 17 (t4 -> l8 = p16)

    if (LAST) {
        // Final perm preserves amp bit 0 and is a bijection -> skip; sum lo lanes.
        float acc = 0.f;
#pragma unroll
        for (int j = 0; j < 8; j++) {
            float rr = flo(re[j]), ii = flo(im[j]);
            acc += rr * rr + ii * ii;
        }
#pragma unroll
        for (int o = 16; o > 0; o >>= 1)
            acc += __shfl_xor_sync(0xffffffffu, acc, o);
        __syncthreads();
        float* red = reinterpret_cast<float*>(sm);
        if ((t & 31u) == 0) red[t >> 5] = acc;
        __syncthreads();
        if (t == 0) {
            float v = 0.f;
#pragma unroll
            for (int w = 0; w < THREADS / 32; w++) v += red[w];
            atomicAdd(out, v);
        }
        return;
    }

    // perm on locals (targets l1..10), store to d_sA
#pragma unroll
    for (int j = 0; j < 8; j++) {
        unsigned l = r2i(t, j);
        unsigned u = l ^ ((l >> 1) & 0x554u);
        unsigned zh = u ^ ((u >> 1) & 0x2AAu);
        unsigned a = (zh & 1u) | (((zh >> 1) & 7u) << 1) | (blk << 4)
                   | (((zh >> 4) & 0xFFu) << 12);
        d_sA[a] = packf4(re[j], im[j]);
    }
}

extern "C" void kernel_launch(void* const* d_in, const int* in_sizes, int n_in,
                              void* d_out, int out_size) {
    const float* feat  = (const float*)d_in[0];
    const float* param = (const float*)d_in[1];
    float* out = (float*)d_out;

    cudaFuncSetAttribute(passA_kernel<0, true >, cudaFuncAttributeMaxDynamicSharedMemorySize, SMEMB);
    cudaFuncSetAttribute(passA_kernel<1, false>, cudaFuncAttributeMaxDynamicSharedMemorySize, SMEMB);
    cudaFuncSetAttribute(passA_kernel<2, false>, cudaFuncAttributeMaxDynamicSharedMemorySize, SMEMB);
    cudaFuncSetAttribute(passB_kernel<0, false>, cudaFuncAttributeMaxDynamicSharedMemorySize, SMEMB);
    cudaFuncSetAttribute(passB_kernel<1, false>, cudaFuncAttributeMaxDynamicSharedMemorySize, SMEMB);
    cudaFuncSetAttribute(passB_kernel<2, true >, cudaFuncAttributeMaxDynamicSharedMemorySize, SMEMB);

    passA_kernel<0, true ><<<NBLK, THREADS, SMEMB>>>(feat, param, out);
    passB_kernel<0, false><<<NBLK, THREADS, SMEMB>>>(out);
    passA_kernel<1, false><<<NBLK, THREADS, SMEMB>>>(feat, param, out);
    passB_kernel<1, false><<<NBLK, THREADS, SMEMB>>>(out);
    passA_kernel<2, false><<<NBLK, THREADS, SMEMB>>>(feat, param, out);
    passB_kernel<2, true ><<<NBLK, THREADS, SMEMB>>>(out);
}

// round 16
// speedup vs baseline: 1.0279x; 1.0279x over previous
#include <cuda_runtime.h>
#include <math.h>

// 21-qubit / 3-layer QNN statevector sim, inter-pass layout staging (R11 champion)
// + Programmatic Dependent Launch to overlap the 5 kernel boundaries.
// Pair format: float4(re(2h),re(2h+1),im(2h),im(2h+1)); amp bit k <-> qubit 20-k;
// amp bit 0 = float4 lane; pair bit b = amp bit b+1.
//
// Storage layouts (a = storage address, h = logical pair index):
//   S_B: a = h0 | h[9..19]<<1 | h[1..8]<<12   (written by passA, read by passB)
//   S_A: a = h0 | h[9..11]<<1 | h[1..8]<<4 | h[12..19]<<12  (written by passB, read by passA)
// Both readers see their 12 tile bits as the LOW 12 address bits -> coalesced loads.
//
// passA: Rots amps 0..12 + CNOT targets 0..9 (perm + lane swap folded into store).
// passB: Rots amps 13..20 + CNOT targets 10..19 (perm folded into store).
// 2 rounds/pass, 1 smem trip; shuffle-gates on lane bits; layer0 A does gate prep.

#define NQ      21
#define NPAIR   (1u << 20)
#define THREADS 512
#define TILEP   4096
#define SMEMB   (TILEP * 16 + 768)
#define NBLK    256

typedef unsigned long long u64;

__device__ float4 d_state[NPAIR];

struct Gate2 { u64 p, q, mq, r, mr, s, ms; };
__device__ Gate2 d_gates[3][NQ];
struct Gate0 { u64 v[6]; };              // (p,p)(r,-r)(-q,q)(-s,-s)(q,-q)(s,s)
__device__ Gate0 d_gate0[3];

__device__ __forceinline__ u64 fma2(u64 a, u64 b, u64 c) {
    u64 d; asm("fma.rn.f32x2 %0,%1,%2,%3;" : "=l"(d) : "l"(a), "l"(b), "l"(c)); return d;
}
__device__ __forceinline__ u64 mul2(u64 a, u64 b) {
    u64 d; asm("mul.rn.f32x2 %0,%1,%2;" : "=l"(d) : "l"(a), "l"(b)); return d;
}
__device__ __forceinline__ float flo(u64 v) { return __uint_as_float((unsigned)v); }
__device__ __forceinline__ float fhi(u64 v) { return __uint_as_float((unsigned)(v >> 32)); }
__device__ __forceinline__ u64 fpack(float a, float b) {
    return (u64)__float_as_uint(a) | ((u64)__float_as_uint(b) << 32);
}
__device__ __forceinline__ u64 swap64(u64 v) { return (v >> 32) | (v << 32); }
__device__ __forceinline__ unsigned sw(unsigned l) { return l ^ ((l >> 3) & 7u); }

__device__ __forceinline__ void gate_coeffs(const float* __restrict__ pp,
                                            float& p, float& q, float& r, float& sv) {
    float phi = pp[0], th = pp[1], om = pp[2];
    float s, c;   sincosf(0.5f * th, &s, &c);
    float sa, ca; sincosf(0.5f * (phi + om), &sa, &ca);
    float sb, cb; sincosf(0.5f * (phi - om), &sb, &cb);
    p = ca * c; q = -sa * c; r = -cb * s; sv = -sb * s;
}

template<int S>
__device__ __forceinline__ void vgate(u64 (&re)[8], u64 (&im)[8], const u64* __restrict__ g) {
    const u64 p = g[0], q = g[1], mq = g[2], r = g[3], mr = g[4], s = g[5], ms = g[6];
#pragma unroll
    for (int j = 0; j < 8; j++) {
        if (j & S) continue;
        const int j1 = j | S;
        u64 xr = re[j], xi = im[j], yr = re[j1], yi = im[j1];
        u64 nr0 = fma2(ms, yi, fma2(r,  yr, fma2(mq, xi, mul2(p,  xr))));
        u64 ni0 = fma2(r,  yi, fma2(s,  yr, fma2(p,  xi, mul2(q,  xr))));
        u64 nr1 = fma2(q,  yi, fma2(p,  yr, fma2(ms, xi, mul2(mr, xr))));
        u64 ni1 = fma2(p,  yi, fma2(mq, yr, fma2(mr, xi, mul2(s,  xr))));
        re[j] = nr0; im[j] = ni0; re[j1] = nr1; im[j1] = ni1;
    }
}

template<int B>
__device__ __forceinline__ void hgate(u64 (&re)[8], u64 (&im)[8], const u64* __restrict__ g) {
    const u64 p = g[0], s = g[5], ms = g[6];
    const bool hi = (threadIdx.x >> B) & 1;
    const u64 A  = hi ? g[1] : g[2];
    const u64 C  = hi ? g[2] : g[1];
    const u64 Bc = hi ? g[4] : g[3];
#pragma unroll
    for (int j = 0; j < 8; j++) {
        u64 wr = __shfl_xor_sync(0xffffffffu, re[j], 1 << B);
        u64 wi = __shfl_xor_sync(0xffffffffu, im[j], 1 << B);
        u64 nr = fma2(ms, wi, fma2(Bc, wr, fma2(A, im[j], mul2(p, re[j]))));
        u64 ni = fma2(Bc, wi, fma2(s,  wr, fma2(p, im[j], mul2(C, re[j]))));
        re[j] = nr; im[j] = ni;
    }
}

__device__ __forceinline__ void sgate2(u64 (&re)[8], u64 (&im)[8], const u64* __restrict__ g) {
    const u64 pp = g[0], rmr = g[1], mqq = g[2], msms = g[3], qmq = g[4], ss = g[5];
#pragma unroll
    for (int j = 0; j < 8; j++) {
        u64 sre = swap64(re[j]), sim = swap64(im[j]);
        u64 nr = fma2(msms, sim, fma2(mqq, im[j], fma2(rmr, sre, mul2(pp,  re[j]))));
        u64 ni = fma2(rmr,  sim, fma2(pp,  im[j], fma2(ss,  sre, mul2(qmq, re[j]))));
        re[j] = nr; im[j] = ni;
    }
}

__device__ __forceinline__ float4 packf4(u64 r, u64 i) {
    return make_float4(flo(r), fhi(r), flo(i), fhi(i));
}
__device__ __forceinline__ void unpackf4(float4 v, u64& r, u64& i) {
    r = fpack(v.x, v.y); i = fpack(v.z, v.w);
}

// r2 layout (both passes): t0..3->l0..3, t5->l4, j->l5..7, t4->l8, t6..8->l9..11
__device__ __forceinline__ unsigned r2i(unsigned t, unsigned j) {
    return (t & 15u) | (((t >> 5) & 1u) << 4) | (j << 5)
         | (((t >> 4) & 1u) << 8) | ((t >> 6) << 9);
}

// ============================ pass A ============================
// FIRST: reads feat (identity), locals = pairs 0..11.
// else : reads S_A, locals: l0=pair0, l1..3=pairs 9..11, l4..11=pairs 1..8.
// Both store S_B with CNOT perm (targets amps 0..9) + lane swap folded in.
template<int LAYER, bool FIRST>
__global__ void __launch_bounds__(THREADS, 2)
passA_kernel(const float* __restrict__ feat, const float* __restrict__ param,
             float* __restrict__ out) {
    cudaGridDependencySynchronize();       // PDL: wait for predecessor kernel
    extern __shared__ char smraw[];
    float4* sm = reinterpret_cast<float4*>(smraw);
    u64* gsm = reinterpret_cast<u64*>(smraw + TILEP * 16);
    const unsigned t   = threadIdx.x;
    const unsigned blk = blockIdx.x;
    u64 re[8], im[8];

    if (FIRST) {
        if (t < 3 * NQ) {
            const int layer = t / NQ, bit = t % NQ, qubit = 20 - bit;
            float p, q, r, sv;
            gate_coeffs(param + (layer * NQ + qubit) * 3, p, q, r, sv);
            Gate2 g;
            g.p  = fpack(p, p);    g.q  = fpack(q, q);   g.mq = fpack(-q, -q);
            g.r  = fpack(r, r);    g.mr = fpack(-r, -r);
            g.s  = fpack(sv, sv);  g.ms = fpack(-sv, -sv);
            if (blk == 0) d_gates[layer][bit] = g;
            if (layer == 0 && bit >= 1 && bit <= 12) {
                u64* dst = gsm + 6 + (bit - 1) * 7;
                dst[0] = g.p;  dst[1] = g.q;  dst[2] = g.mq; dst[3] = g.r;
                dst[4] = g.mr; dst[5] = g.s;  dst[6] = g.ms;
            }
            if (bit == 0) {
                Gate0 g0;
                g0.v[0] = fpack(p, p);    g0.v[1] = fpack(r, -r);
                g0.v[2] = fpack(-q, q);   g0.v[3] = fpack(-sv, -sv);
                g0.v[4] = fpack(q, -q);   g0.v[5] = fpack(sv, sv);
                if (blk == 0) d_gate0[layer] = g0;
                if (layer == 0) {
#pragma unroll
                    for (int k = 0; k < 6; k++) gsm[k] = g0.v[k];
                }
            }
        }
        if (blk == 0 && t == 0) out[0] = 0.f;
    } else {
        if (t < 6)  gsm[t] = reinterpret_cast<const u64*>(&d_gate0[LAYER])[t];
        if (t < 84) gsm[6 + t] = reinterpret_cast<const u64*>(&d_gates[LAYER][1])[t];
    }

    // r1 load: l = t | (j<<9); FIRST from feat (identity), else from S_A (contiguous)
#pragma unroll
    for (int j = 0; j < 8; j++) {
        unsigned l = t | (j << 9);
        if (FIRST) {
            float2 fv = reinterpret_cast<const float2*>(feat)[(blk << 12) | l];
            re[j] = fpack(fv.x, fv.y); im[j] = 0ull;
        } else {
            unpackf4(d_state[(blk << 12) | l], re[j], im[j]);
        }
    }
    __syncthreads();

    sgate2(re, im, gsm);                        // amp 0
    if (FIRST) {
        hgate<0>(re, im, gsm + 6);              // amp 1  (l0 = pair 0)
        hgate<1>(re, im, gsm + 13);             // amp 2
        hgate<2>(re, im, gsm + 20);             // amp 3
        hgate<3>(re, im, gsm + 27);             // amp 4
        hgate<4>(re, im, gsm + 34);             // amp 5
        vgate<1>(re, im, gsm + 69);             // amp 10 (l9)
        vgate<2>(re, im, gsm + 76);             // amp 11
        vgate<4>(re, im, gsm + 83);             // amp 12
    } else {
        hgate<0>(re, im, gsm + 6);              // amp 1  (l0 = pair 0)
        hgate<1>(re, im, gsm + 69);             // amp 10 (l1 = pair 9)
        hgate<2>(re, im, gsm + 76);             // amp 11
        hgate<3>(re, im, gsm + 83);             // amp 12
        hgate<4>(re, im, gsm + 13);             // amp 2  (l4 = pair 1)
        vgate<1>(re, im, gsm + 48);             // amp 7  (l9 = pair 6)
        vgate<2>(re, im, gsm + 55);             // amp 8
        vgate<4>(re, im, gsm + 62);             // amp 9
    }
#pragma unroll
    for (int j = 0; j < 8; j++) sm[sw(t | (j << 9))] = packf4(re[j], im[j]);
    __syncthreads();

    // r2
#pragma unroll
    for (int j = 0; j < 8; j++) unpackf4(sm[sw(r2i(t, j))], re[j], im[j]);
    if (FIRST) {
        vgate<1>(re, im, gsm + 41);             // amp 6 (l5 = pair 5)
        vgate<2>(re, im, gsm + 48);             // amp 7
        vgate<4>(re, im, gsm + 55);             // amp 8
        hgate<4>(re, im, gsm + 62);             // amp 9 (l8 = pair 8)
    } else {
        vgate<1>(re, im, gsm + 20);             // amp 3 (l5 = pair 2)
        vgate<2>(re, im, gsm + 27);             // amp 4
        vgate<4>(re, im, gsm + 34);             // amp 5
        hgate<4>(re, im, gsm + 41);             // amp 6 (l8 = pair 5)
    }

    // perm (targets amps 0..9) in pair space, then store to S_B
#pragma unroll
    for (int j = 0; j < 8; j++) {
        unsigned l = r2i(t, j);
        unsigned z = FIRST ? l
            : ((l & 1u) | (((l >> 4) & 0xFFu) << 1) | (((l >> 1) & 7u) << 9));
        unsigned u = z ^ ((z >> 1) & 0x155u);
        unsigned zh = u ^ ((u >> 1) & 0xAAu);
        unsigned a = (zh & 1u) | (((zh >> 9) & 7u) << 1) | (blk << 4)
                   | (((zh >> 1) & 0xFFu) << 12);
        float4 v = packf4(re[j], im[j]);
        d_state[a] = (zh & 1u) ? make_float4(v.y, v.x, v.w, v.z) : v;
    }
    cudaTriggerProgrammaticLaunchCompletion();  // PDL: allow successor to launch
}

// ============================ pass B ============================
// Reads S_B (contiguous): locals l0 = pair 0 (amp1 spectator), l1..11 = pairs 9..19.
// Stores S_A with CNOT perm (targets amps 10..19 = locals 1..10) folded in.
template<int LAYER, bool LAST>
__global__ void __launch_bounds__(THREADS, 2)
passB_kernel(float* __restrict__ out) {
    cudaGridDependencySynchronize();       // PDL: wait for predecessor kernel
    extern __shared__ char smraw[];
    float4* sm = reinterpret_cast<float4*>(smraw);
    u64* gsm = reinterpret_cast<u64*>(smraw + TILEP * 16);
    const unsigned t = threadIdx.x;
    const unsigned blk = blockIdx.x;
    u64 re[8], im[8];

    if (t < 56) gsm[t] = reinterpret_cast<const u64*>(&d_gates[LAYER][13])[t];

    // r1 load (contiguous): l = t | (j<<9)
#pragma unroll
    for (int j = 0; j < 8; j++)
        unpackf4(d_state[(blk << 12) | (t | (j << 9))], re[j], im[j]);
    __syncthreads();

    hgate<4>(re, im, gsm + 0);            // amp 13 (l4 = pair 12)
    vgate<1>(re, im, gsm + 35);           // amp 18 (l9 = pair 17)
    vgate<2>(re, im, gsm + 42);           // amp 19
    vgate<4>(re, im, gsm + 49);           // amp 20
#pragma unroll
    for (int j = 0; j < 8; j++) sm[sw(t | (j << 9))] = packf4(re[j], im[j]);
    __syncthreads();

    // r2: j = locals 5,6,7 = amps 14,15,16; lane bit 4 -> local 8 = amp 17
#pragma unroll
    for (int j = 0; j < 8; j++) unpackf4(sm[sw(r2i(t, j))], re[j], im[j]);
    vgate<1>(re, im, gsm + 7);            // amp 14
    vgate<2>(re, im, gsm + 14);           // amp 15
    vgate<4>(re, im, gsm + 21);           // amp 16
    hgate<4>(re, im, gsm + 28);           // amp 17

    if (LAST) {
        float acc = 0.f;
#pragma unroll
        for (int j = 0; j < 8; j++) {
            float rr = flo(re[j]), ii = flo(im[j]);
            acc += rr * rr + ii * ii;
        }
#pragma unroll
        for (int o = 16; o > 0; o >>= 1)
            acc += __shfl_xor_sync(0xffffffffu, acc, o);
        __syncthreads();
        float* red = reinterpret_cast<float*>(sm);
        if ((t & 31u) == 0) red[t >> 5] = acc;
        __syncthreads();
        if (t == 0) {
            float v = 0.f;
#pragma unroll
            for (int w = 0; w < THREADS / 32; w++) v += red[w];
            atomicAdd(out, v);
        }
        return;
    }

    // perm on locals, then store to S_A
#pragma unroll
    for (int j = 0; j < 8; j++) {
        unsigned l = r2i(t, j);
        unsigned u = l ^ ((l >> 1) & 0x554u);
        unsigned zh = u ^ ((u >> 1) & 0x2AAu);
        unsigned a = (zh & 1u) | (((zh >> 1) & 7u) << 1) | (blk << 4)
                   | (((zh >> 4) & 0xFFu) << 12);
        d_state[a] = packf4(re[j], im[j]);
    }
    cudaTriggerProgrammaticLaunchCompletion();  // PDL: allow successor to launch
}

extern "C" void kernel_launch(void* const* d_in, const int* in_sizes, int n_in,
                              void* d_out, int out_size) {
    const float* feat  = (const float*)d_in[0];
    const float* param = (const float*)d_in[1];
    float* out = (float*)d_out;

    cudaFuncSetAttribute(passA_kernel<0, true >, cudaFuncAttributeMaxDynamicSharedMemorySize, SMEMB);
    cudaFuncSetAttribute(passA_kernel<1, false>, cudaFuncAttributeMaxDynamicSharedMemorySize, SMEMB);
    cudaFuncSetAttribute(passA_kernel<2, false>, cudaFuncAttributeMaxDynamicSharedMemorySize, SMEMB);
    cudaFuncSetAttribute(passB_kernel<0, false>, cudaFuncAttributeMaxDynamicSharedMemorySize, SMEMB);
    cudaFuncSetAttribute(passB_kernel<1, false>, cudaFuncAttributeMaxDynamicSharedMemorySize, SMEMB);
    cudaFuncSetAttribute(passB_kernel<2, true >, cudaFuncAttributeMaxDynamicSharedMemorySize, SMEMB);

    // First kernel: plain launch. Successors: PDL (programmatic stream serialization).
    passA_kernel<0, true ><<<NBLK, THREADS, SMEMB>>>(feat, param, out);

    cudaLaunchConfig_t cfg = {};
    cfg.gridDim = dim3(NBLK);
    cfg.blockDim = dim3(THREADS);
    cfg.dynamicSmemBytes = SMEMB;
    cfg.stream = 0;
    cudaLaunchAttribute attrs[1];
    attrs[0].id = cudaLaunchAttributeProgrammaticStreamSerialization;
    attrs[0].val.programmaticStreamSerializationAllowed = 1;
    cfg.attrs = attrs;
    cfg.numAttrs = 1;

    cudaLaunchKernelEx(&cfg, passB_kernel<0, false>, out);
    cudaLaunchKernelEx(&cfg, passA_kernel<1, false>, feat, param, out);
    cudaLaunchKernelEx(&cfg, passB_kernel<1, false>, out);
    cudaLaunchKernelEx(&cfg, passA_kernel<2, false>, feat, param, out);
    cudaLaunchKernelEx(&cfg, passB_kernel<2, true >, out);
}

// round 17
// speedup vs baseline: 1.0284x; 1.0004x over previous
#include <cuda_runtime.h>
#include <math.h>

// 21-qubit / 3-layer QNN statevector sim, inter-pass layout staging (R11 champion)
// + deep PDL: early triggers, pre-sync gate staging in successors.
// Pair format: float4(re(2h),re(2h+1),im(2h),im(2h+1)); amp bit k <-> qubit 20-k;
// amp bit 0 = float4 lane; pair bit b = amp bit b+1.
//
// Storage layouts (a = storage address, h = logical pair index):
//   S_B: a = h0 | h[9..19]<<1 | h[1..8]<<12   (written by passA, read by passB)
//   S_A: a = h0 | h[9..11]<<1 | h[1..8]<<4 | h[12..19]<<12  (written by passB, read by passA)
// Both readers see their 12 tile bits as the LOW 12 address bits -> coalesced loads.
//
// passA: Rots amps 0..12 + CNOT targets 0..9 (perm + lane swap folded into store).
// passB: Rots amps 13..20 + CNOT targets 10..19 (perm folded into store).
// Gate-table chain: A0 computes+publishes d_gates, __threadfence, THEN triggers, so
// every later kernel (launchable only through that trigger chain) sees the tables;
// A1/A2/B1/B2 stage them pre-sync. B0 stages post-sync (immediate successor).

#define NQ      21
#define NPAIR   (1u << 20)
#define THREADS 512
#define TILEP   4096
#define SMEMB   (TILEP * 16 + 768)
#define NBLK    256

typedef unsigned long long u64;

__device__ float4 d_state[NPAIR];

struct Gate2 { u64 p, q, mq, r, mr, s, ms; };
__device__ Gate2 d_gates[3][NQ];
struct Gate0 { u64 v[6]; };              // (p,p)(r,-r)(-q,q)(-s,-s)(q,-q)(s,s)
__device__ Gate0 d_gate0[3];

__device__ __forceinline__ u64 fma2(u64 a, u64 b, u64 c) {
    u64 d; asm("fma.rn.f32x2 %0,%1,%2,%3;" : "=l"(d) : "l"(a), "l"(b), "l"(c)); return d;
}
__device__ __forceinline__ u64 mul2(u64 a, u64 b) {
    u64 d; asm("mul.rn.f32x2 %0,%1,%2;" : "=l"(d) : "l"(a), "l"(b)); return d;
}
__device__ __forceinline__ float flo(u64 v) { return __uint_as_float((unsigned)v); }
__device__ __forceinline__ float fhi(u64 v) { return __uint_as_float((unsigned)(v >> 32)); }
__device__ __forceinline__ u64 fpack(float a, float b) {
    return (u64)__float_as_uint(a) | ((u64)__float_as_uint(b) << 32);
}
__device__ __forceinline__ u64 swap64(u64 v) { return (v >> 32) | (v << 32); }
__device__ __forceinline__ unsigned sw(unsigned l) { return l ^ ((l >> 3) & 7u); }

__device__ __forceinline__ void gate_coeffs(const float* __restrict__ pp,
                                            float& p, float& q, float& r, float& sv) {
    float phi = pp[0], th = pp[1], om = pp[2];
    float s, c;   sincosf(0.5f * th, &s, &c);
    float sa, ca; sincosf(0.5f * (phi + om), &sa, &ca);
    float sb, cb; sincosf(0.5f * (phi - om), &sb, &cb);
    p = ca * c; q = -sa * c; r = -cb * s; sv = -sb * s;
}

template<int S>
__device__ __forceinline__ void vgate(u64 (&re)[8], u64 (&im)[8], const u64* __restrict__ g) {
    const u64 p = g[0], q = g[1], mq = g[2], r = g[3], mr = g[4], s = g[5], ms = g[6];
#pragma unroll
    for (int j = 0; j < 8; j++) {
        if (j & S) continue;
        const int j1 = j | S;
        u64 xr = re[j], xi = im[j], yr = re[j1], yi = im[j1];
        u64 nr0 = fma2(ms, yi, fma2(r,  yr, fma2(mq, xi, mul2(p,  xr))));
        u64 ni0 = fma2(r,  yi, fma2(s,  yr, fma2(p,  xi, mul2(q,  xr))));
        u64 nr1 = fma2(q,  yi, fma2(p,  yr, fma2(ms, xi, mul2(mr, xr))));
        u64 ni1 = fma2(p,  yi, fma2(mq, yr, fma2(mr, xi, mul2(s,  xr))));
        re[j] = nr0; im[j] = ni0; re[j1] = nr1; im[j1] = ni1;
    }
}

template<int B>
__device__ __forceinline__ void hgate(u64 (&re)[8], u64 (&im)[8], const u64* __restrict__ g) {
    const u64 p = g[0], s = g[5], ms = g[6];
    const bool hi = (threadIdx.x >> B) & 1;
    const u64 A  = hi ? g[1] : g[2];
    const u64 C  = hi ? g[2] : g[1];
    const u64 Bc = hi ? g[4] : g[3];
#pragma unroll
    for (int j = 0; j < 8; j++) {
        u64 wr = __shfl_xor_sync(0xffffffffu, re[j], 1 << B);
        u64 wi = __shfl_xor_sync(0xffffffffu, im[j], 1 << B);
        u64 nr = fma2(ms, wi, fma2(Bc, wr, fma2(A, im[j], mul2(p, re[j]))));
        u64 ni = fma2(Bc, wi, fma2(s,  wr, fma2(p, im[j], mul2(C, re[j]))));
        re[j] = nr; im[j] = ni;
    }
}

__device__ __forceinline__ void sgate2(u64 (&re)[8], u64 (&im)[8], const u64* __restrict__ g) {
    const u64 pp = g[0], rmr = g[1], mqq = g[2], msms = g[3], qmq = g[4], ss = g[5];
#pragma unroll
    for (int j = 0; j < 8; j++) {
        u64 sre = swap64(re[j]), sim = swap64(im[j]);
        u64 nr = fma2(msms, sim, fma2(mqq, im[j], fma2(rmr, sre, mul2(pp,  re[j]))));
        u64 ni = fma2(rmr,  sim, fma2(pp,  im[j], fma2(ss,  sre, mul2(qmq, re[j]))));
        re[j] = nr; im[j] = ni;
    }
}

__device__ __forceinline__ float4 packf4(u64 r, u64 i) {
    return make_float4(flo(r), fhi(r), flo(i), fhi(i));
}
__device__ __forceinline__ void unpackf4(float4 v, u64& r, u64& i) {
    r = fpack(v.x, v.y); i = fpack(v.z, v.w);
}

// r2 layout (both passes): t0..3->l0..3, t5->l4, j->l5..7, t4->l8, t6..8->l9..11
__device__ __forceinline__ unsigned r2i(unsigned t, unsigned j) {
    return (t & 15u) | (((t >> 5) & 1u) << 4) | (j << 5)
         | (((t >> 4) & 1u) << 8) | ((t >> 6) << 9);
}

// ============================ pass A ============================
// FIRST: reads feat (identity), locals = pairs 0..11; computes + publishes gates.
// else : reads S_A, locals: l0=pair0, l1..3=pairs 9..11, l4..11=pairs 1..8;
//        stages gates PRE-sync (published by A0, fenced before A0's trigger).
// Both store S_B with CNOT perm (targets amps 0..9) + lane swap folded in.
template<int LAYER, bool FIRST>
__global__ void __launch_bounds__(THREADS, 2)
passA_kernel(const float* __restrict__ feat, const float* __restrict__ param,
             float* __restrict__ out) {
    extern __shared__ char smraw[];
    float4* sm = reinterpret_cast<float4*>(smraw);
    u64* gsm = reinterpret_cast<u64*>(smraw + TILEP * 16);
    const unsigned t   = threadIdx.x;
    const unsigned blk = blockIdx.x;
    u64 re[8], im[8];

    if (FIRST) {
        if (t < 3 * NQ) {
            const int layer = t / NQ, bit = t % NQ, qubit = 20 - bit;
            float p, q, r, sv;
            gate_coeffs(param + (layer * NQ + qubit) * 3, p, q, r, sv);
            Gate2 g;
            g.p  = fpack(p, p);    g.q  = fpack(q, q);   g.mq = fpack(-q, -q);
            g.r  = fpack(r, r);    g.mr = fpack(-r, -r);
            g.s  = fpack(sv, sv);  g.ms = fpack(-sv, -sv);
            if (blk == 0) d_gates[layer][bit] = g;
            if (layer == 0 && bit >= 1 && bit <= 12) {
                u64* dst = gsm + 6 + (bit - 1) * 7;
                dst[0] = g.p;  dst[1] = g.q;  dst[2] = g.mq; dst[3] = g.r;
                dst[4] = g.mr; dst[5] = g.s;  dst[6] = g.ms;
            }
            if (bit == 0) {
                Gate0 g0;
                g0.v[0] = fpack(p, p);    g0.v[1] = fpack(r, -r);
                g0.v[2] = fpack(-q, q);   g0.v[3] = fpack(-sv, -sv);
                g0.v[4] = fpack(q, -q);   g0.v[5] = fpack(sv, sv);
                if (blk == 0) d_gate0[layer] = g0;
                if (layer == 0) {
#pragma unroll
                    for (int k = 0; k < 6; k++) gsm[k] = g0.v[k];
                }
            }
            if (blk == 0) __threadfence();       // publish gate tables...
        }
        if (blk == 0 && t == 0) out[0] = 0.f;
        cudaTriggerProgrammaticLaunchCompletion(); // ...before the launch chain opens
        __syncthreads();                           // gsm visible
    } else {
        // pre-sync prolog: gates come from A0, guaranteed published (fence->trigger chain)
        if (t < 6)  gsm[t] = reinterpret_cast<const u64*>(&d_gate0[LAYER])[t];
        if (t < 84) gsm[6 + t] = reinterpret_cast<const u64*>(&d_gates[LAYER][1])[t];
        __syncthreads();                           // gsm visible
        cudaTriggerProgrammaticLaunchCompletion(); // open successor launch
        cudaGridDependencySynchronize();           // wait for predecessor's d_state
    }

    // r1 load: l = t | (j<<9); FIRST from feat (identity), else from S_A (contiguous)
#pragma unroll
    for (int j = 0; j < 8; j++) {
        unsigned l = t | (j << 9);
        if (FIRST) {
            float2 fv = reinterpret_cast<const float2*>(feat)[(blk << 12) | l];
            re[j] = fpack(fv.x, fv.y); im[j] = 0ull;
        } else {
            unpackf4(d_state[(blk << 12) | l], re[j], im[j]);
        }
    }

    sgate2(re, im, gsm);                        // amp 0
    if (FIRST) {
        hgate<0>(re, im, gsm + 6);              // amp 1  (l0 = pair 0)
        hgate<1>(re, im, gsm + 13);             // amp 2
        hgate<2>(re, im, gsm + 20);             // amp 3
        hgate<3>(re, im, gsm + 27);             // amp 4
        hgate<4>(re, im, gsm + 34);             // amp 5
        vgate<1>(re, im, gsm + 69);             // amp 10 (l9)
        vgate<2>(re, im, gsm + 76);             // amp 11
        vgate<4>(re, im, gsm + 83);             // amp 12
    } else {
        hgate<0>(re, im, gsm + 6);              // amp 1  (l0 = pair 0)
        hgate<1>(re, im, gsm + 69);             // amp 10 (l1 = pair 9)
        hgate<2>(re, im, gsm + 76);             // amp 11
        hgate<3>(re, im, gsm + 83);             // amp 12
        hgate<4>(re, im, gsm + 13);             // amp 2  (l4 = pair 1)
        vgate<1>(re, im, gsm + 48);             // amp 7  (l9 = pair 6)
        vgate<2>(re, im, gsm + 55);             // amp 8
        vgate<4>(re, im, gsm + 62);             // amp 9
    }
#pragma unroll
    for (int j = 0; j < 8; j++) sm[sw(t | (j << 9))] = packf4(re[j], im[j]);
    __syncthreads();

    // r2
#pragma unroll
    for (int j = 0; j < 8; j++) unpackf4(sm[sw(r2i(t, j))], re[j], im[j]);
    if (FIRST) {
        vgate<1>(re, im, gsm + 41);             // amp 6 (l5 = pair 5)
        vgate<2>(re, im, gsm + 48);             // amp 7
        vgate<4>(re, im, gsm + 55);             // amp 8
        hgate<4>(re, im, gsm + 62);             // amp 9 (l8 = pair 8)
    } else {
        vgate<1>(re, im, gsm + 20);             // amp 3 (l5 = pair 2)
        vgate<2>(re, im, gsm + 27);             // amp 4
        vgate<4>(re, im, gsm + 34);             // amp 5
        hgate<4>(re, im, gsm + 41);             // amp 6 (l8 = pair 5)
    }

    // perm (targets amps 0..9) in pair space, then store to S_B
#pragma unroll
    for (int j = 0; j < 8; j++) {
        unsigned l = r2i(t, j);
        unsigned z = FIRST ? l
            : ((l & 1u) | (((l >> 4) & 0xFFu) << 1) | (((l >> 1) & 7u) << 9));
        unsigned u = z ^ ((z >> 1) & 0x155u);
        unsigned zh = u ^ ((u >> 1) & 0xAAu);
        unsigned a = (zh & 1u) | (((zh >> 9) & 7u) << 1) | (blk << 4)
                   | (((zh >> 1) & 0xFFu) << 12);
        float4 v = packf4(re[j], im[j]);
        d_state[a] = (zh & 1u) ? make_float4(v.y, v.x, v.w, v.z) : v;
    }
}

// ============================ pass B ============================
// Reads S_B (contiguous): locals l0 = pair 0 (amp1 spectator), l1..11 = pairs 9..19.
// LAYER==0 stages gates post-sync (A0 is immediate predecessor); else pre-sync.
// Stores S_A with CNOT perm (targets amps 10..19 = locals 1..10) folded in.
template<int LAYER, bool LAST>
__global__ void __launch_bounds__(THREADS, 2)
passB_kernel(float* __restrict__ out) {
    extern __shared__ char smraw[];
    float4* sm = reinterpret_cast<float4*>(smraw);
    u64* gsm = reinterpret_cast<u64*>(smraw + TILEP * 16);
    const unsigned t = threadIdx.x;
    const unsigned blk = blockIdx.x;
    u64 re[8], im[8];

    if (LAYER > 0) {
        if (t < 56) gsm[t] = reinterpret_cast<const u64*>(&d_gates[LAYER][13])[t];
        __syncthreads();                           // gsm visible
        cudaTriggerProgrammaticLaunchCompletion();
        cudaGridDependencySynchronize();
        // r1 load (contiguous)
#pragma unroll
        for (int j = 0; j < 8; j++)
            unpackf4(d_state[(blk << 12) | (t | (j << 9))], re[j], im[j]);
    } else {
        cudaTriggerProgrammaticLaunchCompletion();
        cudaGridDependencySynchronize();
        if (t < 56) gsm[t] = reinterpret_cast<const u64*>(&d_gates[LAYER][13])[t];
#pragma unroll
        for (int j = 0; j < 8; j++)
            unpackf4(d_state[(blk << 12) | (t | (j << 9))], re[j], im[j]);
        __syncthreads();                           // gsm visible
    }

    hgate<4>(re, im, gsm + 0);            // amp 13 (l4 = pair 12)
    vgate<1>(re, im, gsm + 35);           // amp 18 (l9 = pair 17)
    vgate<2>(re, im, gsm + 42);           // amp 19
    vgate<4>(re, im, gsm + 49);           // amp 20
#pragma unroll
    for (int j = 0; j < 8; j++) sm[sw(t | (j << 9))] = packf4(re[j], im[j]);
    __syncthreads();

    // r2: j = locals 5,6,7 = amps 14,15,16; lane bit 4 -> local 8 = amp 17
#pragma unroll
    for (int j = 0; j < 8; j++) unpackf4(sm[sw(r2i(t, j))], re[j], im[j]);
    vgate<1>(re, im, gsm + 7);            // amp 14
    vgate<2>(re, im, gsm + 14);           // amp 15
    vgate<4>(re, im, gsm + 21);           // amp 16
    hgate<4>(re, im, gsm + 28);           // amp 17

    if (LAST) {
        float acc = 0.f;
#pragma unroll
        for (int j = 0; j < 8; j++) {
            float rr = flo(re[j]), ii = flo(im[j]);
            acc += rr * rr + ii * ii;
        }
#pragma unroll
        for (int o = 16; o > 0; o >>= 1)
            acc += __shfl_xor_sync(0xffffffffu, acc, o);
        __syncthreads();
        float* red = reinterpret_cast<float*>(sm);
        if ((t & 31u) == 0) red[t >> 5] = acc;
        __syncthreads();
        if (t == 0) {
            float v = 0.f;
#pragma unroll
            for (int w = 0; w < THREADS / 32; w++) v += red[w];
            atomicAdd(out, v);
        }
        return;
    }

    // perm on locals, then store to S_A
#pragma unroll
    for (int j = 0; j < 8; j++) {
        unsigned l = r2i(t, j);
        unsigned u = l ^ ((l >> 1) & 0x554u);
        unsigned zh = u ^ ((u >> 1) & 0x2AAu);
        unsigned a = (zh & 1u) | (((zh >> 1) & 7u) << 1) | (blk << 4)
                   | (((zh >> 4) & 0xFFu) << 12);
        d_state[a] = packf4(re[j], im[j]);
    }
}

extern "C" void kernel_launch(void* const* d_in, const int* in_sizes, int n_in,
                              void* d_out, int out_size) {
    const float* feat  = (const float*)d_in[0];
    const float* param = (const float*)d_in[1];
    float* out = (float*)d_out;

    cudaFuncSetAttribute(passA_kernel<0, true >, cudaFuncAttributeMaxDynamicSharedMemorySize, SMEMB);
    cudaFuncSetAttribute(passA_kernel<1, false>, cudaFuncAttributeMaxDynamicSharedMemorySize, SMEMB);
    cudaFuncSetAttribute(passA_kernel<2, false>, cudaFuncAttributeMaxDynamicSharedMemorySize, SMEMB);
    cudaFuncSetAttribute(passB_kernel<0, false>, cudaFuncAttributeMaxDynamicSharedMemorySize, SMEMB);
    cudaFuncSetAttribute(passB_kernel<1, false>, cudaFuncAttributeMaxDynamicSharedMemorySize, SMEMB);
    cudaFuncSetAttribute(passB_kernel<2, true >, cudaFuncAttributeMaxDynamicSharedMemorySize, SMEMB);

    // First kernel: plain launch. Successors: PDL (programmatic stream serialization).
    passA_kernel<0, true ><<<NBLK, THREADS, SMEMB>>>(feat, param, out);

    cudaLaunchConfig_t cfg = {};
    cfg.gridDim = dim3(NBLK);
    cfg.blockDim = dim3(THREADS);
    cfg.dynamicSmemBytes = SMEMB;
    cfg.stream = 0;
    cudaLaunchAttribute attrs[1];
    attrs[0].id = cudaLaunchAttributeProgrammaticStreamSerialization;
    attrs[0].val.programmaticStreamSerializationAllowed = 1;
    cfg.attrs = attrs;
    cfg.numAttrs = 1;

    cudaLaunchKernelEx(&cfg, passB_kernel<0, false>, out);
    cudaLaunchKernelEx(&cfg, passA_kernel<1, false>, feat, param, out);
    cudaLaunchKernelEx(&cfg, passB_kernel<1, false>, out);
    cudaLaunchKernelEx(&cfg, passA_kernel<2, false>, feat, param, out);
    cudaLaunchKernelEx(&cfg, passB_kernel<2, true >, out);
}